// round 3
// baseline (speedup 1.0000x reference)
#include <cuda_runtime.h>
#include <math.h>

typedef unsigned long long ull;

#define NB 4
#define NC 128
#define NH 64
#define NW 64
#define NHW 4096
#define NG 32
#define NTD 512
#define SCALE_Q 0.088388347648318447f  /* 1/sqrt(128) */

// ------------------------- static scratch (no allocations) -------------------------
static __device__ float g_act [NB * NC * NHW];   // GN+SiLU activations (both GNs)
static __device__ float g_h1  [NB * NC * NHW];   // conv1 out + temb
static __device__ float g_h1T [NB * NHW * NC];   // h1 transposed [b][w][h][c], * 1/sqrt(C)
static __device__ float g_cbuf[NB * NC * NHW];   // cond 1x1 projection
static __device__ float g_h2  [NB * NC * NHW];   // h1 + embed (+ attn via atomics)
static __device__ float g_temb[NB * NC];
static __device__ float g_mean[NB * NG];
static __device__ float g_rstd[NB * NG];

// ------------------------- packed f32x2 helpers (sm_103a FFMA2) -------------------------
__device__ __forceinline__ void fma2(ull& d, ull a, ull b) {
    asm("fma.rn.f32x2 %0, %1, %2, %0;" : "+l"(d) : "l"(a), "l"(b));
}
__device__ __forceinline__ ull dup2(float x) {
    ull r;
    asm("mov.b64 %0, {%1, %2};" : "=l"(r) : "f"(x), "f"(x));
    return r;
}
__device__ __forceinline__ float2 unp2(ull v) {
    float2 r;
    asm("mov.b64 {%0, %1}, %2;" : "=f"(r.x), "=f"(r.y) : "l"(v));
    return r;
}
__device__ __forceinline__ float siluf(float x) { return x / (1.0f + __expf(-x)); }

// ------------------------- group-norm statistics: block per (b, g) -------------------------
__global__ void __launch_bounds__(256) gn_stats_k(const float* __restrict__ src,
                                                  float* __restrict__ mean,
                                                  float* __restrict__ rstd) {
    int bg = blockIdx.x;                 // b*32+g; group = 4 contiguous channels
    const float4* p = (const float4*)(src + bg * 16384);
    float s = 0.f, ss = 0.f;
    for (int i = threadIdx.x; i < 4096; i += 256) {
        float4 v = p[i];
        s  += v.x + v.y + v.z + v.w;
        ss += v.x * v.x + v.y * v.y + v.z * v.z + v.w * v.w;
    }
    for (int off = 16; off; off >>= 1) {
        s  += __shfl_down_sync(0xffffffffu, s,  off);
        ss += __shfl_down_sync(0xffffffffu, ss, off);
    }
    __shared__ float ws[8], wss[8];
    int wid = threadIdx.x >> 5, lane = threadIdx.x & 31;
    if (lane == 0) { ws[wid] = s; wss[wid] = ss; }
    __syncthreads();
    if (threadIdx.x == 0) {
        float ts = 0.f, tss = 0.f;
        for (int i = 0; i < 8; i++) { ts += ws[i]; tss += wss[i]; }
        float m = ts * (1.f / 16384.f);
        float var = tss * (1.f / 16384.f) - m * m;
        mean[bg] = m;
        rstd[bg] = rsqrtf(var + 1e-5f);
    }
}

// ------------------------- GN apply + SiLU (elementwise, float4) -------------------------
__global__ void __launch_bounds__(256) gn_apply_k(const float* __restrict__ src,
                                                  const float* __restrict__ mean,
                                                  const float* __restrict__ rstd,
                                                  const float* __restrict__ sc,
                                                  const float* __restrict__ bi,
                                                  float* __restrict__ dst) {
    int i = blockIdx.x * 256 + threadIdx.x;      // float4 index, total 524288
    int c  = (i >> 10) & 127;
    int bg = (i >> 17) * 32 + (c >> 2);
    float m = mean[bg], r = rstd[bg];
    float a = r * sc[c];
    float b = bi[c] - m * a;
    float4 v = ((const float4*)src)[i];
    v.x = siluf(v.x * a + b);
    v.y = siluf(v.y * a + b);
    v.z = siluf(v.z * a + b);
    v.w = siluf(v.w * a + b);
    ((float4*)dst)[i] = v;
}

// ------------------------- time embedding: temb = silu(t) @ W^T + b -------------------------
__global__ void __launch_bounds__(128) temb_k(const float* __restrict__ t,
                                              const float* __restrict__ mw,
                                              const float* __restrict__ mb,
                                              float* __restrict__ temb) {
    __shared__ float st[NTD];
    int b = blockIdx.x, tid = threadIdx.x;
    for (int k = tid; k < NTD; k += 128) st[k] = siluf(t[b * NTD + k]);
    __syncthreads();
    float acc = mb[tid];
    const float* wr = mw + tid * NTD;
#pragma unroll 8
    for (int k = 0; k < NTD; k++) acc += st[k] * wr[k];
    temb[b * NC + tid] = acc;
}

// ------------------------- 3x3 conv, pad 1. MODE 0: +bias+temb; MODE 1: +bias+residual ---
template <int MODE>
__global__ void __launch_bounds__(256) conv3x3_k(const float* __restrict__ src,
                                                 const float* __restrict__ wgt,
                                                 const float* __restrict__ bias,
                                                 const float* __restrict__ temb,
                                                 const float* __restrict__ resid,
                                                 float* __restrict__ dst) {
    __shared__ float in_s[8 * 3 * 66];      // [ci][kh][wp]
    __shared__ float wt_s[64 * 73];         // [co][ci*9+k], stride 73 (bank-spread)
    int co0 = blockIdx.x * 64;
    int h   = blockIdx.y;
    int b   = blockIdx.z;
    int t   = threadIdx.x;
    int co_l = (t & 31) * 2;                // 2 output channels per thread
    int w0   = (t >> 5) * 8;                // 8 output columns, warp-uniform

    float acc[2][8];
#pragma unroll
    for (int c2 = 0; c2 < 2; c2++)
#pragma unroll
        for (int w = 0; w < 8; w++) acc[c2][w] = 0.f;

    for (int chunk = 0; chunk < 16; chunk++) {
        int ci0 = chunk * 8;
        __syncthreads();
        // load input rows h-1..h+1 for 8 ci, zero-padded
        for (int idx = t; idx < 1584; idx += 256) {
            int ci = idx / 198, r = idx % 198, kh = r / 66, wp = r % 66;
            int hh = h - 1 + kh, wc = wp - 1;
            float v = 0.f;
            if (hh >= 0 && hh < 64 && wc >= 0 && wc < 64)
                v = src[((b * 128 + ci0 + ci) * 64 + hh) * 64 + wc];
            in_s[ci * 198 + kh * 66 + wp] = v;
        }
        // load weights for 64 co x 8 ci x 9
        for (int idx = t; idx < 4608; idx += 256) {
            int co = idx / 72, r = idx % 72;
            wt_s[co * 73 + r] = wgt[(co0 + co) * 1152 + ci0 * 9 + r];
        }
        __syncthreads();
#pragma unroll
        for (int ci = 0; ci < 8; ci++) {
#pragma unroll
            for (int kh = 0; kh < 3; kh++) {
                float rin[10];
                const float* ip = &in_s[ci * 198 + kh * 66 + w0];
#pragma unroll
                for (int j = 0; j < 10; j++) rin[j] = ip[j];
#pragma unroll
                for (int c2 = 0; c2 < 2; c2++) {
                    const float* wr = &wt_s[(co_l + c2) * 73 + ci * 9 + kh * 3];
                    float wa = wr[0], wb = wr[1], wc = wr[2];
#pragma unroll
                    for (int w = 0; w < 8; w++)
                        acc[c2][w] += wa * rin[w] + wb * rin[w + 1] + wc * rin[w + 2];
                }
            }
        }
    }
#pragma unroll
    for (int c2 = 0; c2 < 2; c2++) {
        int co = co0 + co_l + c2;
        float add = bias[co] + (MODE == 0 ? temb[b * 128 + co] : 0.f);
        int base = ((b * 128 + co) * 64 + h) * 64 + w0;
#pragma unroll
        for (int w = 0; w < 8; w++) {
            float v = acc[c2][w] + add;
            if (MODE == 1) v += resid[base + w];
            dst[base + w] = v;
        }
    }
}

// ------------------------- cond 1x1 projection (f32x2) -------------------------
__global__ void __launch_bounds__(256) cond1x1_k(const float* __restrict__ cond,
                                                 const float* __restrict__ wt,
                                                 const float* __restrict__ bias,
                                                 float* __restrict__ out) {
    __shared__ float ct[128 * 64];
    int uv0 = blockIdx.x * 64;
    int b = blockIdx.y, t = threadIdx.x;
    for (int i = 0; i < 32; i++) {
        int idx = t + i * 256;
        ct[idx] = cond[(b * 128 + (idx >> 6)) * 4096 + uv0 + (idx & 63)];
    }
    __syncthreads();
    int co = t & 127, uh = t >> 7;
    ull acc[16];
#pragma unroll
    for (int j = 0; j < 16; j++) acc[j] = 0ull;
    const float* wrow = wt + co * 128;
    for (int ci = 0; ci < 128; ci++) {
        ull wv = dup2(__ldg(wrow + ci));
        const ull* kr = (const ull*)&ct[ci * 64 + uh * 32];
#pragma unroll
        for (int j = 0; j < 16; j++) fma2(acc[j], wv, kr[j]);
    }
    float bv = bias[co];
    float* op = out + (b * 128 + co) * 4096 + uv0 + uh * 32;
#pragma unroll
    for (int j = 0; j < 16; j++) {
        float2 v = unp2(acc[j]);
        op[2 * j]     = v.x + bv;
        op[2 * j + 1] = v.y + bv;
    }
}

// ------------------------- transpose + scale: h1[b,c,h,w] -> h1T[b,w,h,c]/sqrt(C) ---------
__global__ void __launch_bounds__(256) transpose_k(const float* __restrict__ h1,
                                                   float* __restrict__ h1T) {
    __shared__ float sm[128 * 65];
    int h = blockIdx.x, b = blockIdx.y, t = threadIdx.x;
    const float* src = h1 + ((b * 128) * 64 + h) * 64;   // element (c,w) at c*4096 + w
    for (int i = 0; i < 32; i++) {
        int idx = t + i * 256;
        int c = idx >> 6, w = idx & 63;
        sm[c * 65 + w] = src[c * 4096 + w] * SCALE_Q;
    }
    __syncthreads();
    for (int i = 0; i < 32; i++) {
        int idx = t + i * 256;
        int w = idx >> 7, c = idx & 127;
        h1T[((b * 64 + w) * 64 + h) * 128 + c] = sm[c * 65 + w];
    }
}

// ------------------------- prefill: h2 = h1 + contrast_embed[aim[b]] -------------------------
__global__ void __launch_bounds__(256) prefill_k(const float* __restrict__ h1,
                                                 const float* __restrict__ emb,
                                                 const int* __restrict__ aim,
                                                 float* __restrict__ h2) {
    int i = blockIdx.x * 256 + threadIdx.x;   // float4 index
    int b = i >> 17, c = (i >> 10) & 127;
    float e = emb[aim[b] * 128 + c];
    float4 v = ((const float4*)h1)[i];
    v.x += e; v.y += e; v.z += e; v.w += e;
    ((float4*)h2)[i] = v;
}

// ------------------------- fused attention: per (b, w, uv-quarter) -------------------------
// S[h][u] = sum_c A[h][c]*K[c][u]; softmax over h per column; O[h][c] += P[h][u]*K[c][u]
#define ATT_SMEM_FLOATS (64 * 129 + 128 * 66 + 64 * 66 + 256 + 256 + 64 + 64)
__global__ void __launch_bounds__(256, 2) attn_k(const float* __restrict__ A,
                                                 const float* __restrict__ K,
                                                 float* __restrict__ h2) {
    extern __shared__ float sm[];
    float* As   = sm;                        // [64][129]
    float* Ks   = As + 64 * 129;             // [128][66]
    float* Ss   = Ks + 128 * 66;             // [64][66]
    float* redm = Ss + 64 * 66;              // [4][64]
    float* reds = redm + 256;                // [4][64]

    int b = blockIdx.x, w = blockIdx.y, chunk = blockIdx.z;
    int t = threadIdx.x;

    const float* Ab = A + ((b * 64 + w) * 64) * 128;
    for (int i = 0; i < 32; i++) {
        int idx = t + i * 256;
        As[(idx >> 7) * 129 + (idx & 127)] = Ab[idx];
    }

    ull o2[4][8];
#pragma unroll
    for (int i = 0; i < 4; i++)
#pragma unroll
        for (int j = 0; j < 8; j++) o2[i][j] = 0ull;

    int h1g = (t & 15) * 4, u1g = (t >> 4) * 4;   // GEMM1 tile
    int hb  = (t & 15) * 4, cb  = (t >> 4) * 8;   // GEMM2 tile
    int su  = t & 63, qq = t >> 6;                 // softmax lane

    const float* Kb = K + b * 128 * 4096 + chunk * 1024;

    for (int tile = 0; tile < 16; tile++) {
        __syncthreads();                           // previous tile's readers done
        const float* Kt = Kb + tile * 64;
        for (int i = 0; i < 32; i++) {
            int idx = t + i * 256;
            Ks[(idx >> 6) * 66 + (idx & 63)] = Kt[(idx >> 6) * 4096 + (idx & 63)];
        }
        __syncthreads();

        // ---- GEMM1: S = A^T K (pack along u) ----
        ull s2[4][2];
#pragma unroll
        for (int i = 0; i < 4; i++) { s2[i][0] = 0ull; s2[i][1] = 0ull; }
#pragma unroll 2
        for (int c = 0; c < 128; c++) {
            ull k0 = *(const ull*)&Ks[c * 66 + u1g];
            ull k1 = *(const ull*)&Ks[c * 66 + u1g + 2];
#pragma unroll
            for (int i = 0; i < 4; i++) {
                ull av = dup2(As[(h1g + i) * 129 + c]);
                fma2(s2[i][0], av, k0);
                fma2(s2[i][1], av, k1);
            }
        }
#pragma unroll
        for (int i = 0; i < 4; i++) {
            *(ull*)&Ss[(h1g + i) * 66 + u1g]     = s2[i][0];
            *(ull*)&Ss[(h1g + i) * 66 + u1g + 2] = s2[i][1];
        }
        __syncthreads();

        // ---- softmax over h (64) per column u ----
        {
            float m = -1e30f;
#pragma unroll
            for (int hh = 0; hh < 16; hh++)
                m = fmaxf(m, Ss[(qq * 16 + hh) * 66 + su]);
            redm[qq * 64 + su] = m;
            __syncthreads();
            float cm = fmaxf(fmaxf(redm[su], redm[64 + su]),
                             fmaxf(redm[128 + su], redm[192 + su]));
            float ps = 0.f;
#pragma unroll
            for (int hh = 0; hh < 16; hh++) {
                float e = __expf(Ss[(qq * 16 + hh) * 66 + su] - cm);
                Ss[(qq * 16 + hh) * 66 + su] = e;
                ps += e;
            }
            reds[qq * 64 + su] = ps;
            __syncthreads();
            float rs = 1.f / (reds[su] + reds[64 + su] + reds[128 + su] + reds[192 + su]);
#pragma unroll
            for (int hh = 0; hh < 16; hh++)
                Ss[(qq * 16 + hh) * 66 + su] *= rs;
        }
        __syncthreads();

        // ---- GEMM2: O += P K^T (pack along u = reduction dim) ----
        for (int up = 0; up < 32; up++) {
            int u = 2 * up;
            ull p2[4];
#pragma unroll
            for (int i = 0; i < 4; i++) p2[i] = *(const ull*)&Ss[(hb + i) * 66 + u];
            ull k2[8];
#pragma unroll
            for (int j = 0; j < 8; j++) k2[j] = *(const ull*)&Ks[(cb + j) * 66 + u];
#pragma unroll
            for (int i = 0; i < 4; i++)
#pragma unroll
                for (int j = 0; j < 8; j++) fma2(o2[i][j], p2[i], k2[j]);
        }
    }

    // ---- epilogue: horizontal add + atomic accumulate into h2[b,c,h,w] ----
#pragma unroll
    for (int i = 0; i < 4; i++)
#pragma unroll
        for (int j = 0; j < 8; j++) {
            float2 v = unp2(o2[i][j]);
            atomicAdd(&h2[((b * 128 + cb + j) * 64 + hb + i) * 64 + w], v.x + v.y);
        }
}

// ------------------------- launch -------------------------
extern "C" void kernel_launch(void* const* d_in, const int* in_sizes, int n_in,
                              void* d_out, int out_size) {
    const float* x    = (const float*)d_in[0];
    const float* tt   = (const float*)d_in[1];
    const int*   aim  = (const int*)d_in[2];
    const float* cond = (const float*)d_in[3];
    const float* g1s  = (const float*)d_in[4];
    const float* g1b  = (const float*)d_in[5];
    const float* c1w  = (const float*)d_in[6];
    const float* c1b  = (const float*)d_in[7];
    const float* mw   = (const float*)d_in[8];
    const float* mb   = (const float*)d_in[9];
    const float* cw   = (const float*)d_in[10];
    const float* cbi  = (const float*)d_in[11];
    const float* g2s  = (const float*)d_in[12];
    const float* g2b  = (const float*)d_in[13];
    const float* c2w  = (const float*)d_in[14];
    const float* c2b  = (const float*)d_in[15];
    const float* emb  = (const float*)d_in[16];
    float* out = (float*)d_out;

    float *act, *h1, *h1T, *cbuf, *h2, *temb, *mean, *rstd;
    cudaGetSymbolAddress((void**)&act,  g_act);
    cudaGetSymbolAddress((void**)&h1,   g_h1);
    cudaGetSymbolAddress((void**)&h1T,  g_h1T);
    cudaGetSymbolAddress((void**)&cbuf, g_cbuf);
    cudaGetSymbolAddress((void**)&h2,   g_h2);
    cudaGetSymbolAddress((void**)&temb, g_temb);
    cudaGetSymbolAddress((void**)&mean, g_mean);
    cudaGetSymbolAddress((void**)&rstd, g_rstd);

    cudaFuncSetAttribute(attn_k, cudaFuncAttributeMaxDynamicSharedMemorySize,
                         ATT_SMEM_FLOATS * 4);

    gn_stats_k<<<128, 256>>>(x, mean, rstd);
    gn_apply_k<<<2048, 256>>>(x, mean, rstd, g1s, g1b, act);
    temb_k<<<4, 128>>>(tt, mw, mb, temb);
    conv3x3_k<0><<<dim3(2, 64, 4), 256>>>(act, c1w, c1b, temb, nullptr, h1);
    cond1x1_k<<<dim3(64, 4), 256>>>(cond, cw, cbi, cbuf);
    transpose_k<<<dim3(64, 4), 256>>>(h1, h1T);
    prefill_k<<<2048, 256>>>(h1, emb, aim, h2);
    attn_k<<<dim3(4, 64, 4), 256, ATT_SMEM_FLOATS * 4>>>(h1T, cbuf, h2);
    gn_stats_k<<<128, 256>>>(h2, mean, rstd);
    gn_apply_k<<<2048, 256>>>(h2, mean, rstd, g2s, g2b, act);
    conv3x3_k<1><<<dim3(2, 64, 4), 256>>>(act, c2w, c2b, nullptr, x, out);
}

// round 4
// speedup vs baseline: 1.1627x; 1.1627x over previous
#include <cuda_runtime.h>
#include <math.h>

typedef unsigned long long ull;

#define NB 4
#define NC 128
#define NHW 4096
#define NG 32
#define NTD 512
#define SCALE_Q 0.088388347648318447f  /* 1/sqrt(128) */

// ------------------------- static scratch (no allocations) -------------------------
static __device__ float g_act [NB * NC * NHW];   // GN+SiLU activations (both GNs)
static __device__ float g_h1  [NB * NC * NHW];   // conv1 out + temb
static __device__ float g_h1T [NB * NHW * NC];   // h1 transposed [b][w][h][c], * 1/sqrt(C)
static __device__ float g_cbuf[NB * NC * NHW];   // cond 1x1 projection
static __device__ float g_h2  [NB * NC * NHW];   // h1 + embed (+ attn via atomics)
static __device__ float g_temb[NB * NC];
static __device__ float g_mean[NB * NG];
static __device__ float g_rstd[NB * NG];

// ------------------------- packed f32x2 helpers (sm_103a FFMA2) -------------------------
__device__ __forceinline__ void fma2(ull& d, ull a, ull b) {
    asm("fma.rn.f32x2 %0, %1, %2, %0;" : "+l"(d) : "l"(a), "l"(b));
}
__device__ __forceinline__ ull dup2(float x) {
    ull r;
    asm("mov.b64 %0, {%1, %2};" : "=l"(r) : "f"(x), "f"(x));
    return r;
}
__device__ __forceinline__ ull pk2(float lo, float hi) {
    ull r;
    asm("mov.b64 %0, {%1, %2};" : "=l"(r) : "f"(lo), "f"(hi));
    return r;
}
__device__ __forceinline__ float2 unp2(ull v) {
    float2 r;
    asm("mov.b64 {%0, %1}, %2;" : "=f"(r.x), "=f"(r.y) : "l"(v));
    return r;
}
__device__ __forceinline__ float siluf(float x) { return x / (1.0f + __expf(-x)); }

// ------------------------- group-norm statistics: block per (b, g) -------------------------
__global__ void __launch_bounds__(256) gn_stats_k(const float* __restrict__ src,
                                                  float* __restrict__ mean,
                                                  float* __restrict__ rstd) {
    int bg = blockIdx.x;                 // b*32+g; group = 4 contiguous channels
    const float4* p = (const float4*)(src + bg * 16384);
    float s = 0.f, ss = 0.f;
    for (int i = threadIdx.x; i < 4096; i += 256) {
        float4 v = p[i];
        s  += v.x + v.y + v.z + v.w;
        ss += v.x * v.x + v.y * v.y + v.z * v.z + v.w * v.w;
    }
    for (int off = 16; off; off >>= 1) {
        s  += __shfl_down_sync(0xffffffffu, s,  off);
        ss += __shfl_down_sync(0xffffffffu, ss, off);
    }
    __shared__ float ws[8], wss[8];
    int wid = threadIdx.x >> 5, lane = threadIdx.x & 31;
    if (lane == 0) { ws[wid] = s; wss[wid] = ss; }
    __syncthreads();
    if (threadIdx.x == 0) {
        float ts = 0.f, tss = 0.f;
        for (int i = 0; i < 8; i++) { ts += ws[i]; tss += wss[i]; }
        float m = ts * (1.f / 16384.f);
        float var = tss * (1.f / 16384.f) - m * m;
        mean[bg] = m;
        rstd[bg] = rsqrtf(var + 1e-5f);
    }
}

// ------------------------- GN apply + SiLU (elementwise, float4) -------------------------
__global__ void __launch_bounds__(256) gn_apply_k(const float* __restrict__ src,
                                                  const float* __restrict__ mean,
                                                  const float* __restrict__ rstd,
                                                  const float* __restrict__ sc,
                                                  const float* __restrict__ bi,
                                                  float* __restrict__ dst) {
    int i = blockIdx.x * 256 + threadIdx.x;      // float4 index, total 524288
    int c  = (i >> 10) & 127;
    int bg = (i >> 17) * 32 + (c >> 2);
    float m = mean[bg], r = rstd[bg];
    float a = r * sc[c];
    float b = bi[c] - m * a;
    float4 v = ((const float4*)src)[i];
    v.x = siluf(v.x * a + b);
    v.y = siluf(v.y * a + b);
    v.z = siluf(v.z * a + b);
    v.w = siluf(v.w * a + b);
    ((float4*)dst)[i] = v;
}

// ------------------------- time embedding: temb = silu(t) @ W^T + b -------------------------
__global__ void __launch_bounds__(128) temb_k(const float* __restrict__ t,
                                              const float* __restrict__ mw,
                                              const float* __restrict__ mb,
                                              float* __restrict__ temb) {
    __shared__ float st[NTD];
    int b = blockIdx.x, tid = threadIdx.x;
    for (int k = tid; k < NTD; k += 128) st[k] = siluf(t[b * NTD + k]);
    __syncthreads();
    float acc = mb[tid];
    const float* wr = mw + tid * NTD;
#pragma unroll 8
    for (int k = 0; k < NTD; k++) acc += st[k] * wr[k];
    temb[b * NC + tid] = acc;
}

// ------------------------- 3x3 conv, pad 1, f32x2 inner. MODE 0: +temb; MODE 1: +residual ---
template <int MODE>
__global__ void __launch_bounds__(256) conv3x3_k(const float* __restrict__ src,
                                                 const float* __restrict__ wgt,
                                                 const float* __restrict__ bias,
                                                 const float* __restrict__ temb,
                                                 const float* __restrict__ resid,
                                                 float* __restrict__ dst) {
    __shared__ float in_s[8 * 3 * 66];      // [ci][kh][wp]
    __shared__ float wt_s[64 * 73];         // [co][ci*9+k], stride 73 (bank-spread)
    int co0 = blockIdx.x * 64;
    int h   = blockIdx.y;
    int b   = blockIdx.z;
    int t   = threadIdx.x;
    int co_l = (t & 31) * 2;                // 2 output channels per thread
    int w0   = (t >> 5) * 8;                // 8 output columns, warp-uniform

    ull acc2[2][4];                          // [c2][w-pair]
#pragma unroll
    for (int c2 = 0; c2 < 2; c2++)
#pragma unroll
        for (int p = 0; p < 4; p++) acc2[c2][p] = 0ull;

    for (int chunk = 0; chunk < 16; chunk++) {
        int ci0 = chunk * 8;
        __syncthreads();
        // load input rows h-1..h+1 for 8 ci, zero-padded
        for (int idx = t; idx < 1584; idx += 256) {
            int ci = idx / 198, r = idx % 198, kh = r / 66, wp = r % 66;
            int hh = h - 1 + kh, wc = wp - 1;
            float v = 0.f;
            if (hh >= 0 && hh < 64 && wc >= 0 && wc < 64)
                v = src[((b * 128 + ci0 + ci) * 64 + hh) * 64 + wc];
            in_s[ci * 198 + kh * 66 + wp] = v;
        }
        // load weights for 64 co x 8 ci x 9
        for (int idx = t; idx < 4608; idx += 256) {
            int co = idx / 72, r = idx % 72;
            wt_s[co * 73 + r] = wgt[(co0 + co) * 1152 + ci0 * 9 + r];
        }
        __syncthreads();
#pragma unroll
        for (int ci = 0; ci < 8; ci++) {
#pragma unroll
            for (int kh = 0; kh < 3; kh++) {
                const ull* ep = (const ull*)&in_s[ci * 198 + kh * 66 + w0]; // 8B aligned
                ull e0[5];
#pragma unroll
                for (int p = 0; p < 5; p++) e0[p] = ep[p];
                float2 f0 = unp2(e0[0]), f1 = unp2(e0[1]), f2 = unp2(e0[2]),
                       f3 = unp2(e0[3]), f4 = unp2(e0[4]);
                ull e1[4];
                e1[0] = pk2(f0.y, f1.x);
                e1[1] = pk2(f1.y, f2.x);
                e1[2] = pk2(f2.y, f3.x);
                e1[3] = pk2(f3.y, f4.x);
#pragma unroll
                for (int c2 = 0; c2 < 2; c2++) {
                    const float* wr = &wt_s[(co_l + c2) * 73 + ci * 9 + kh * 3];
                    ull wad = dup2(wr[0]), wbd = dup2(wr[1]), wcd = dup2(wr[2]);
#pragma unroll
                    for (int p = 0; p < 4; p++) {
                        fma2(acc2[c2][p], wad, e0[p]);
                        fma2(acc2[c2][p], wbd, e1[p]);
                        fma2(acc2[c2][p], wcd, e0[p + 1]);
                    }
                }
            }
        }
    }
#pragma unroll
    for (int c2 = 0; c2 < 2; c2++) {
        int co = co0 + co_l + c2;
        float add = bias[co] + (MODE == 0 ? temb[b * 128 + co] : 0.f);
        int base = ((b * 128 + co) * 64 + h) * 64 + w0;
#pragma unroll
        for (int p = 0; p < 4; p++) {
            float2 v = unp2(acc2[c2][p]);
            float o0 = v.x + add, o1 = v.y + add;
            if (MODE == 1) { o0 += resid[base + 2 * p]; o1 += resid[base + 2 * p + 1]; }
            dst[base + 2 * p]     = o0;
            dst[base + 2 * p + 1] = o1;
        }
    }
}

// ------------------------- cond 1x1 projection (f32x2) -------------------------
__global__ void __launch_bounds__(256) cond1x1_k(const float* __restrict__ cond,
                                                 const float* __restrict__ wt,
                                                 const float* __restrict__ bias,
                                                 float* __restrict__ out) {
    __shared__ float ct[128 * 64];
    int uv0 = blockIdx.x * 64;
    int b = blockIdx.y, t = threadIdx.x;
    for (int i = 0; i < 32; i++) {
        int idx = t + i * 256;
        ct[idx] = cond[(b * 128 + (idx >> 6)) * 4096 + uv0 + (idx & 63)];
    }
    __syncthreads();
    int co = t & 127, uh = t >> 7;
    ull acc[16];
#pragma unroll
    for (int j = 0; j < 16; j++) acc[j] = 0ull;
    const float* wrow = wt + co * 128;
    for (int ci = 0; ci < 128; ci++) {
        ull wv = dup2(__ldg(wrow + ci));
        const ull* kr = (const ull*)&ct[ci * 64 + uh * 32];
#pragma unroll
        for (int j = 0; j < 16; j++) fma2(acc[j], wv, kr[j]);
    }
    float bv = bias[co];
    float* op = out + (b * 128 + co) * 4096 + uv0 + uh * 32;
#pragma unroll
    for (int j = 0; j < 16; j++) {
        float2 v = unp2(acc[j]);
        op[2 * j]     = v.x + bv;
        op[2 * j + 1] = v.y + bv;
    }
}

// ------------------------- transpose + scale: h1[b,c,h,w] -> h1T[b,w,h,c]/sqrt(C) ---------
__global__ void __launch_bounds__(256) transpose_k(const float* __restrict__ h1,
                                                   float* __restrict__ h1T) {
    __shared__ float sm[128 * 65];
    int h = blockIdx.x, b = blockIdx.y, t = threadIdx.x;
    const float* src = h1 + ((b * 128) * 64 + h) * 64;   // element (c,w) at c*4096 + w
    for (int i = 0; i < 32; i++) {
        int idx = t + i * 256;
        int c = idx >> 6, w = idx & 63;
        sm[c * 65 + w] = src[c * 4096 + w] * SCALE_Q;
    }
    __syncthreads();
    for (int i = 0; i < 32; i++) {
        int idx = t + i * 256;
        int w = idx >> 7, c = idx & 127;
        h1T[((b * 64 + w) * 64 + h) * 128 + c] = sm[c * 65 + w];
    }
}

// ------------------------- prefill: h2 = h1 + contrast_embed[aim[b]] -------------------------
__global__ void __launch_bounds__(256) prefill_k(const float* __restrict__ h1,
                                                 const float* __restrict__ emb,
                                                 const int* __restrict__ aim,
                                                 float* __restrict__ h2) {
    int i = blockIdx.x * 256 + threadIdx.x;   // float4 index
    int b = i >> 17, c = (i >> 10) & 127;
    float e = emb[aim[b] * 128 + c];
    float4 v = ((const float4*)h1)[i];
    v.x += e; v.y += e; v.z += e; v.w += e;
    ((float4*)h2)[i] = v;
}

// ------------------------- fused attention: per (b, w, uv-quarter) -------------------------
// Layouts (all per-tile in smem):
//   As2[h][c2]  ull, stride 65:  (A[h][2c2], A[h][2c2+1])   -- tile-invariant
//   KsT[u][c2]  ull, stride 65:  (K[2c2][u], K[2c2+1][u])
//   SsT[u][h]   f32, stride 65
// GEMM1: s2[h][u] (c-parity packed) += As2 * KsT       (reduction packed over c)
// GEMM2: o2[h][c2] (output packed over c-pair) += dup(P[h][u]) * KsT[u][c2]
#define ATT_SMEM_BYTES (64 * 65 * 8 + 64 * 65 * 8 + 64 * 65 * 4 + 2048)
__global__ void __launch_bounds__(256, 2) attn_k(const float* __restrict__ A,
                                                 const float* __restrict__ K,
                                                 float* __restrict__ h2) {
    extern __shared__ char smraw[];
    ull*   As2  = (ull*)smraw;
    ull*   KsT  = As2 + 64 * 65;
    float* SsT  = (float*)(KsT + 64 * 65);
    float* redm = SsT + 64 * 65;
    float* reds = redm + 256;

    int b = blockIdx.x, w = blockIdx.y, chunk = blockIdx.z;
    int t = threadIdx.x;

    // load A tile (64h x 128c), float alias of As2: index h*130 + c  (write CF)
    {
        float* Asf = (float*)As2;
        const float* Ab = A + ((b * 64 + w) * 64) * 128;
        for (int i = 0; i < 32; i++) {
            int idx = t + i * 256;
            Asf[(idx >> 7) * 130 + (idx & 127)] = Ab[idx];
        }
    }

    ull o2[4][4];
#pragma unroll
    for (int i = 0; i < 4; i++)
#pragma unroll
        for (int j = 0; j < 4; j++) o2[i][j] = 0ull;

    int q  = t & 15;        // h rows: q, q+16, q+32, q+48 (bank-spread)
    int ug = t >> 4;        // GEMM1 u-group / GEMM2 c2-group: 4*ug .. 4*ug+3
    int su = t & 63, qq = t >> 6;   // softmax mapping

    const float* Kb = K + b * 128 * 4096 + chunk * 1024;
    float* KsTf = (float*)KsT;

    for (int tile = 0; tile < 16; tile++) {
        __syncthreads();                           // previous tile's readers done
        const float* Kt = Kb + tile * 64;
        // K tile (128c x 64u) -> KsT[u][c], float alias index u*130 + c
        for (int i = 0; i < 32; i++) {
            int idx = t + i * 256;
            int c = idx >> 6, u = idx & 63;
            KsTf[u * 130 + c] = Kt[c * 4096 + u];
        }
        __syncthreads();

        // ---- GEMM1: S = A K  (c-parity packed reduction) ----
        ull s2[4][4];
#pragma unroll
        for (int i = 0; i < 4; i++)
#pragma unroll
            for (int j = 0; j < 4; j++) s2[i][j] = 0ull;
#pragma unroll 2
        for (int c2 = 0; c2 < 64; c2++) {
            ull a2[4], k2[4];
#pragma unroll
            for (int i = 0; i < 4; i++) a2[i] = As2[(q + 16 * i) * 65 + c2];
#pragma unroll
            for (int j = 0; j < 4; j++) k2[j] = KsT[(4 * ug + j) * 65 + c2];
#pragma unroll
            for (int i = 0; i < 4; i++)
#pragma unroll
                for (int j = 0; j < 4; j++) fma2(s2[i][j], a2[i], k2[j]);
        }
#pragma unroll
        for (int i = 0; i < 4; i++)
#pragma unroll
            for (int j = 0; j < 4; j++) {
                float2 v = unp2(s2[i][j]);
                SsT[(4 * ug + j) * 65 + q + 16 * i] = v.x + v.y;
            }
        __syncthreads();

        // ---- softmax over h (rows of SsT are contiguous in h) ----
        {
            float* Srow = SsT + su * 65 + qq * 16;
            float m = -1e30f;
#pragma unroll
            for (int hh = 0; hh < 16; hh++) m = fmaxf(m, Srow[hh]);
            redm[qq * 64 + su] = m;
            __syncthreads();
            float cm = fmaxf(fmaxf(redm[su], redm[64 + su]),
                             fmaxf(redm[128 + su], redm[192 + su]));
            float ps = 0.f;
#pragma unroll
            for (int hh = 0; hh < 16; hh++) {
                float e = __expf(Srow[hh] - cm);
                Srow[hh] = e;
                ps += e;
            }
            reds[qq * 64 + su] = ps;
            __syncthreads();
            float rs = 1.f / (reds[su] + reds[64 + su] + reds[128 + su] + reds[192 + su]);
#pragma unroll
            for (int hh = 0; hh < 16; hh++) Srow[hh] *= rs;
        }
        __syncthreads();

        // ---- GEMM2: O[h][c-pair] += dup(P[h][u]) * KsT[u][c2] ----
#pragma unroll 2
        for (int u = 0; u < 64; u++) {
            ull pd[4], kt[4];
#pragma unroll
            for (int i = 0; i < 4; i++) pd[i] = dup2(SsT[u * 65 + q + 16 * i]);
#pragma unroll
            for (int j = 0; j < 4; j++) kt[j] = KsT[u * 65 + 4 * ug + j];
#pragma unroll
            for (int i = 0; i < 4; i++)
#pragma unroll
                for (int j = 0; j < 4; j++) fma2(o2[i][j], pd[i], kt[j]);
        }
    }

    // ---- epilogue: atomic accumulate into h2[b,c,h,w] ----
#pragma unroll
    for (int i = 0; i < 4; i++)
#pragma unroll
        for (int j = 0; j < 4; j++) {
            float2 v = unp2(o2[i][j]);
            int c0 = 2 * (4 * ug + j);
            int hh = q + 16 * i;
            atomicAdd(&h2[((b * 128 + c0)     * 64 + hh) * 64 + w], v.x);
            atomicAdd(&h2[((b * 128 + c0 + 1) * 64 + hh) * 64 + w], v.y);
        }
}

// ------------------------- launch -------------------------
extern "C" void kernel_launch(void* const* d_in, const int* in_sizes, int n_in,
                              void* d_out, int out_size) {
    const float* x    = (const float*)d_in[0];
    const float* tt   = (const float*)d_in[1];
    const int*   aim  = (const int*)d_in[2];
    const float* cond = (const float*)d_in[3];
    const float* g1s  = (const float*)d_in[4];
    const float* g1b  = (const float*)d_in[5];
    const float* c1w  = (const float*)d_in[6];
    const float* c1b  = (const float*)d_in[7];
    const float* mw   = (const float*)d_in[8];
    const float* mb   = (const float*)d_in[9];
    const float* cw   = (const float*)d_in[10];
    const float* cbi  = (const float*)d_in[11];
    const float* g2s  = (const float*)d_in[12];
    const float* g2b  = (const float*)d_in[13];
    const float* c2w  = (const float*)d_in[14];
    const float* c2b  = (const float*)d_in[15];
    const float* emb  = (const float*)d_in[16];
    float* out = (float*)d_out;

    float *act, *h1, *h1T, *cbuf, *h2, *temb, *mean, *rstd;
    cudaGetSymbolAddress((void**)&act,  g_act);
    cudaGetSymbolAddress((void**)&h1,   g_h1);
    cudaGetSymbolAddress((void**)&h1T,  g_h1T);
    cudaGetSymbolAddress((void**)&cbuf, g_cbuf);
    cudaGetSymbolAddress((void**)&h2,   g_h2);
    cudaGetSymbolAddress((void**)&temb, g_temb);
    cudaGetSymbolAddress((void**)&mean, g_mean);
    cudaGetSymbolAddress((void**)&rstd, g_rstd);

    cudaFuncSetAttribute(attn_k, cudaFuncAttributeMaxDynamicSharedMemorySize,
                         ATT_SMEM_BYTES);

    gn_stats_k<<<128, 256>>>(x, mean, rstd);
    gn_apply_k<<<2048, 256>>>(x, mean, rstd, g1s, g1b, act);
    temb_k<<<4, 128>>>(tt, mw, mb, temb);
    conv3x3_k<0><<<dim3(2, 64, 4), 256>>>(act, c1w, c1b, temb, nullptr, h1);
    cond1x1_k<<<dim3(64, 4), 256>>>(cond, cw, cbi, cbuf);
    transpose_k<<<dim3(64, 4), 256>>>(h1, h1T);
    prefill_k<<<2048, 256>>>(h1, emb, aim, h2);
    attn_k<<<dim3(4, 64, 4), 256, ATT_SMEM_BYTES>>>(h1T, cbuf, h2);
    gn_stats_k<<<128, 256>>>(h2, mean, rstd);
    gn_apply_k<<<2048, 256>>>(h2, mean, rstd, g2s, g2b, act);
    conv3x3_k<1><<<dim3(2, 64, 4), 256>>>(act, c2w, c2b, nullptr, x, out);
}